// round 14
// baseline (speedup 1.0000x reference)
#include <cuda_runtime.h>
#include <cuda_bf16.h>
#include <math.h>
#include <stdint.h>

#define B 2
#define P 512
#define C 21
#define REG 5
#define DET 100
#define NGRP (B*(C-1))          // 40
#define TOT ((C-1)*P)           // 10240 per image
#define SCORE_THRESH 0.05f
#define NMS_THR 0.5f
#define BBOX_CLIP 4.135166556742356f   // log(1000/16)
#define DEG2RAD 0.017453292519943295f
#define RAD2DEG 57.29577951308232f
#define IMW_M1 1023.0f
#define IMH_M1 799.0f
#define QCAP 131072
#define SQ_CAP 4096
#define FULLM 0xffffffffu
#define CANDCAP 256
#define KMAX 10                 // ceil(TOT / 1024)

// ---------------- device scratch ----------------
__device__ float  g_pr_s[NGRP * P * 5];          // rank-ordered proposals
__device__ float4 g_bx4[NGRP * P];               // rank-ordered clipped aabb
__device__ unsigned long long g_cand[B * TOT];   // kept candidates (key<<32 | ~fi)
__device__ int    g_cnd_n[B];                    // per-image candidate count (k4 resets)
__device__ int    g_queue[NGRP * QCAP];          // pair-queue overflow

// ---------------- exact quad-quad intersection area (matches reference) -----
__device__ float inter_area(const float* __restrict__ p1x, const float* __restrict__ p1y,
                            const float* __restrict__ p2x, const float* __restrict__ p2y)
{
    float px[8], py[8];
    #pragma unroll
    for (int i = 0; i < 4; i++) { px[i] = p1x[i]; py[i] = p1y[i]; }
    int n = 4;

    for (int k = 0; k < 4; k++) {
        float ax = p2x[k], ay = p2y[k];
        int k1 = (k + 1) & 3;
        float dx = p2x[k1] - ax, dy = p2y[k1] - ay;
        float qx[8], qy[8];
        int m = 0;
        for (int i = 0; i < n; i++) {
            float sx = px[i], sy = py[i];
            int ei = (i + 1 == n) ? 0 : (i + 1);
            float ex = px[ei], ey = py[ei];
            float cs = dx * (sy - ay) - dy * (sx - ax);
            float ce = dx * (ey - ay) - dy * (ex - ax);
            float denom = cs - ce;
            float t = cs / ((fabsf(denom) > 1e-12f) ? denom : 1e-12f);
            float ipx = sx + t * (ex - sx);
            float ipy = sy + t * (ey - sy);
            bool s_in = (cs >= 0.0f), e_in = (ce >= 0.0f);
            if (s_in != e_in) { int mm = m < 7 ? m : 7; qx[mm] = ipx; qy[mm] = ipy; m++; }
            if (e_in)         { int mm = m < 7 ? m : 7; qx[mm] = ex;  qy[mm] = ey;  m++; }
        }
        if (m > 8) m = 8;
        n = m;
        for (int i = 0; i < n; i++) { px[i] = qx[i]; py[i] = qy[i]; }
    }
    if (n < 3) return 0.0f;
    float acc = 0.0f;
    for (int i = 0; i < n; i++) {
        int k2 = (i + 1 == n) ? 0 : (i + 1);
        acc += px[i] * py[k2] - px[k2] * py[i];
    }
    return 0.5f * fabsf(acc);
}

// ---------------- kernel: decode + rank + rotated NMS per group -------------
__global__ __launch_bounds__(512)
void k123_sortnms(const float* __restrict__ logits,
                  const float* __restrict__ regr,
                  const float* __restrict__ rrects)
{
    int g = blockIdx.x;                 // 0..39
    int b = g / (C-1);
    int cls = g % (C-1) + 1;
    int tid = threadIdx.x;              // 0..511
    int lane = tid & 31;
    int wid = tid >> 5;

    extern __shared__ float4 smf4[];
    float4* sbb  = smf4;                        // 512 float4 (mnx,mny,mxx,mxy)
    float*  cs   = (float*)(sbb + P);           // 512 compacted scores
    int*    cidx = (int*)(cs + P);              // 512 compacted orig idx
    float*  ptsx = (float*)(cidx + P);          // 512*4
    float*  ptsy = ptsx + 4 * P;                // 512*4
    float*  areaS= ptsy + 4 * P;                // 512
    unsigned* sup = (unsigned*)(areaS + P);     // 512*16
    int* squeue  = (int*)(sup + 16 * P);        // SQ_CAP (reused as dirty list in ph3)
    __shared__ int vcnt, qcnt, Vsh;
    __shared__ unsigned dirty[16];
    __shared__ unsigned keepM[16];

    int row = b * P + tid;

    // ---- softmax score for (row, cls) ----
    const float* lg = &logits[row * C];
    float mx = lg[0];
    #pragma unroll
    for (int i = 1; i < C; i++) mx = fmaxf(mx, lg[i]);
    float ssum = 0.0f, ecls = 0.0f;
    #pragma unroll
    for (int i = 0; i < C; i++) {
        float e = expf(lg[i] - mx);
        ssum += e;
        if (i == cls) ecls = e;
    }
    float s = ecls / ssum;
    bool valid = s > SCORE_THRESH;

    // ---- decode own (row, cls) box into registers ----
    float pp[5];
    {
        float axc = rrects[row*5+0], ayc = rrects[row*5+1];
        float aw  = rrects[row*5+2], ah  = rrects[row*5+3];
        float aa  = rrects[row*5+4];
        const float* d = &regr[row * C * REG + cls * REG];
        float dx = d[0] / 10.0f;
        float dy = d[1] / 10.0f;
        float dw = fminf(d[2] / 5.0f, BBOX_CLIP);
        float dh = fminf(d[3] / 5.0f, BBOX_CLIP);
        float da = d[4] / 3.0f;
        pp[0] = dx * aw + axc;
        pp[1] = dy * ah + ayc;
        pp[2] = expf(dw) * aw;
        pp[3] = expf(dh) * ah;
        pp[4] = da * RAD2DEG + aa;
    }

    // ---- corners + aabb (registers) ----
    float th = pp[4] * DEG2RAD;
    float cth = cosf(th), sth = sinf(th);
    float hx = pp[2] * 0.5f, hy = pp[3] * 0.5f;
    float oxs[4] = {-hx, hx, hx, -hx};
    float oys[4] = {-hy, -hy, hy, hy};
    float cxx[4], cyy[4];
    float mnx = 1e30f, mny = 1e30f, mxx = -1e30f, mxy = -1e30f;
    #pragma unroll
    for (int i = 0; i < 4; i++) {
        float cx = pp[0] + cth * oxs[i] - sth * oys[i];
        float cy = pp[1] + sth * oxs[i] + cth * oys[i];
        cxx[i] = cx; cyy[i] = cy;
        mnx = fminf(mnx, cx); mxx = fmaxf(mxx, cx);
        mny = fminf(mny, cy); mxy = fmaxf(mxy, cy);
    }

    // ---- init shared ----
    if (tid == 0) { vcnt = 0; qcnt = 0; }
    if (tid < 16) dirty[tid] = 0u;
    #pragma unroll
    for (int k = 0; k < 16; k++) sup[k * P + tid] = 0u;
    __syncthreads();

    // ---- compact valid entries ----
    unsigned mbv = __ballot_sync(FULLM, valid);
    int wb = 0;
    if (lane == 0 && mbv) wb = atomicAdd(&vcnt, __popc(mbv));
    wb = __shfl_sync(FULLM, wb, 0);
    if (valid) {
        int p = wb + __popc(mbv & ((1u << lane) - 1u));
        cs[p] = s; cidx[p] = tid;
    }
    __syncthreads();
    int V = vcnt;
    if (tid == 0) Vsh = V;

    // ---- rank valid entries by (score desc, idx asc); scatter own data ----
    int rank = -1;
    if (valid) {
        int r = 0;
        #pragma unroll 4
        for (int i = 0; i < V; i++) {
            float o = cs[i];
            r += (o > s) || (o == s && cidx[i] < tid);
        }
        rank = r;
        #pragma unroll
        for (int i = 0; i < 4; i++) { ptsx[rank*4+i] = cxx[i]; ptsy[rank*4+i] = cyy[i]; }
        sbb[rank] = make_float4(mnx, mny, mxx, mxy);
        areaS[rank] = pp[2] * pp[3];
        #pragma unroll
        for (int k = 0; k < 5; k++) g_pr_s[(g * P + rank) * 5 + k] = pp[k];
        g_bx4[g * P + rank] = make_float4(
            fminf(fmaxf(mnx, 0.0f), IMW_M1),
            fminf(fmaxf(mny, 0.0f), IMH_M1),
            fminf(fmaxf(mxx, 0.0f), IMW_M1),
            fminf(fmaxf(mxy, 0.0f), IMH_M1));
    }
    __syncthreads();

    // ---- phase 1: AABB + IoU-upper-bound precheck -> pair queue ------------
    // lockstep over j (broadcast LDS); each thread owns one (or half a) row.
    if (V > 1) {
        if (V <= 256) {
            // two threads per row: thread -> row tid>>1, j parity tid&1
            int myrow = tid >> 1;
            int par = tid & 1;
            bool rowok = (myrow < V);
            float4 bi; float ai = 0.0f;
            if (rowok) { bi = sbb[myrow]; ai = areaS[myrow]; }
            int maxrow = min(V - 1, ((wid << 4) + 15));   // rows in warp: [16w,16w+16)
            if ((wid << 4) < V) {
                int nk = (maxrow + 1) >> 1;               // j = 2k+par < maxrow
                for (int k = 0; k < nk; k++) {
                    int j = (k << 1) + par;
                    bool act = rowok && (j < myrow);
                    float4 bj = sbb[j];
                    float aj = areaS[j];
                    bool push = false;
                    if (act) {
                        float iw = fminf(bi.z, bj.z) - fmaxf(bi.x, bj.x);
                        float ih = fminf(bi.w, bj.w) - fmaxf(bi.y, bj.y);
                        if (iw > 0.0f && ih > 0.0f) {
                            float ub = fminf(iw * ih, fminf(ai, aj));
                            float bound = ub / (ai + aj - ub + 1e-8f);
                            push = bound > NMS_THR * 0.999f;
                        }
                    }
                    unsigned mb = __ballot_sync(FULLM, push);
                    if (mb) {
                        int ldr = __ffs(mb) - 1;
                        int basep = 0;
                        if (lane == ldr) basep = atomicAdd(&qcnt, __popc(mb));
                        basep = __shfl_sync(FULLM, basep, ldr);
                        if (push) {
                            int pos = basep + __popc(mb & ((1u << lane) - 1u));
                            int enc = (myrow << 16) | j;
                            if (pos < SQ_CAP) squeue[pos] = enc;
                            else g_queue[g * QCAP + (pos - SQ_CAP)] = enc;
                        }
                    }
                }
            }
        } else {
            // one thread per row
            bool rowok = (tid < V);
            float4 bi; float ai = 0.0f;
            if (rowok) { bi = sbb[tid]; ai = areaS[tid]; }
            if ((wid << 5) < V) {
                int maxrow = min(V - 1, (wid << 5) + 31);
                for (int j = 0; j < maxrow; j++) {
                    bool act = rowok && (j < tid);
                    float4 bj = sbb[j];
                    float aj = areaS[j];
                    bool push = false;
                    if (act) {
                        float iw = fminf(bi.z, bj.z) - fmaxf(bi.x, bj.x);
                        float ih = fminf(bi.w, bj.w) - fmaxf(bi.y, bj.y);
                        if (iw > 0.0f && ih > 0.0f) {
                            float ub = fminf(iw * ih, fminf(ai, aj));
                            float bound = ub / (ai + aj - ub + 1e-8f);
                            push = bound > NMS_THR * 0.999f;
                        }
                    }
                    unsigned mb = __ballot_sync(FULLM, push);
                    if (mb) {
                        int ldr = __ffs(mb) - 1;
                        int basep = 0;
                        if (lane == ldr) basep = atomicAdd(&qcnt, __popc(mb));
                        basep = __shfl_sync(FULLM, basep, ldr);
                        if (push) {
                            int pos = basep + __popc(mb & ((1u << lane) - 1u));
                            int enc = (tid << 16) | j;
                            if (pos < SQ_CAP) squeue[pos] = enc;
                            else g_queue[g * QCAP + (pos - SQ_CAP)] = enc;
                        }
                    }
                }
            }
        }
    }
    __syncthreads();

    // ---- phase 2: exact IoU over surviving pairs ----
    int nq = qcnt;
    for (int q = tid; q < nq; q += blockDim.x) {
        int ij = (q < SQ_CAP) ? squeue[q] : g_queue[g * QCAP + (q - SQ_CAP)];
        int i = ij >> 16, j = ij & 0xffff;
        float inter = inter_area(&ptsx[i * 4], &ptsy[i * 4], &ptsx[j * 4], &ptsy[j * 4]);
        float iou = inter / (areaS[i] + areaS[j] - inter + 1e-8f);
        if (iou > NMS_THR) {
            atomicOr(&sup[i * 16 + (j >> 5)], 1u << (j & 31));
            atomicOr(&dirty[i >> 5], 1u << (i & 31));
        }
    }
    __syncthreads();

    // ---- phase 3: sparse greedy scan over dirty rows (warp 0) ----
    if (tid < 32) {
        // build ascending dirty-row list into squeue (reuse; phase 2 done)
        unsigned w = (lane < 16) ? dirty[lane] : 0u;
        int cnt = __popc(w);
        int incl = cnt;
        #pragma unroll
        for (int o = 1; o < 32; o <<= 1) {
            int v = __shfl_up_sync(FULLM, incl, o);
            if (lane >= o) incl += v;
        }
        int nd = __shfl_sync(FULLM, incl, 31);
        {
            int p = incl - cnt;
            unsigned m = w;
            while (m) { int i = (lane << 5) + __ffs(m) - 1; m &= m - 1; squeue[p++] = i; }
        }
        __syncwarp();

        unsigned km = 0u;
        if (lane < 16) {
            int lo = lane * 32;
            int VV = Vsh;
            km = (VV >= lo + 32) ? 0xffffffffu : (VV > lo ? ((1u << (VV - lo)) - 1u) : 0u);
        }
        int icur = (nd > 0) ? squeue[0] : 0;
        unsigned srow = (lane < 16 && nd > 0) ? sup[icur * 16 + lane] : 0u;
        for (int q = 0; q < nd; q++) {
            int inext = (q + 1 < nd) ? squeue[q + 1] : 0;
            unsigned nrow = (lane < 16 && (q + 1) < nd) ? sup[inext * 16 + lane] : 0u;
            bool any = __any_sync(FULLM, (srow & km) != 0u);
            if (any && lane == (icur >> 5)) km &= ~(1u << (icur & 31));
            srow = nrow; icur = inext;
        }
        if (lane < 16) keepM[lane] = km;
    }
    __syncthreads();

    // ---- emit kept candidates to per-image list ----
    bool emit = valid && ((keepM[rank >> 5] >> (rank & 31)) & 1u);
    unsigned mb = __ballot_sync(FULLM, emit);
    if (mb) {
        int ldr = __ffs(mb) - 1;
        int basep = 0;
        if (lane == ldr) basep = atomicAdd(&g_cnd_n[b], __popc(mb));
        basep = __shfl_sync(FULLM, basep, ldr);
        if (emit) {
            int pos = basep + __popc(mb & ((1u << lane) - 1u));
            int fi = (cls - 1) * P + rank;               // flat index within image
            unsigned kk = __float_as_uint(s) ^ 0x80000000u;   // s > 0
            g_cand[b * TOT + pos] =
                ((unsigned long long)kk << 32) | (unsigned)(~fi);
        }
    }
}

// ---------------- kernel 4: histogram top-100 select + output ----------------
__global__ __launch_bounds__(1024)
void k4_topk(float* __restrict__ out)
{
    int b = blockIdx.x;
    int tid = threadIdx.x;
    int lane = tid & 31;

    __shared__ int hist[256];
    __shared__ int nc_sh;
    __shared__ int sel_bin, sel_above, sel_cnt;
    __shared__ int ncand2;
    __shared__ unsigned long long cand[CANDCAP];

    if (tid == 0) nc_sh = g_cnd_n[b];
    __syncthreads();
    int nc = nc_sh;

    // load candidate slots (u64), invalid -> 0
    unsigned hi[KMAX], lo[KMAX];
    #pragma unroll
    for (int i = 0; i < KMAX; i++) {
        int pos = tid + (i << 10);
        unsigned long long u = (pos < nc) ? g_cand[b * TOT + pos] : 0ull;
        hi[i] = (unsigned)(u >> 32);
        lo[i] = (unsigned)u;
    }

    unsigned thr = 0u;
    if (nc > CANDCAP) {
        unsigned prefix = 0u, pmask = 0u;
        int above = 0;
        for (int shift = 24; shift >= 0; shift -= 8) {
            if (tid < 256) hist[tid] = 0;
            __syncthreads();
            // warp-aggregated histogram add
            #pragma unroll
            for (int i = 0; i < KMAX; i++) {
                bool act = hi[i] && ((hi[i] & pmask) == prefix);
                unsigned dig = act ? ((hi[i] >> shift) & 0xFFu) : 0xFFFFFFFFu;
                unsigned mm = __match_any_sync(FULLM, dig);
                int l0 = __ffs(mm) - 1;
                if (act && lane == l0) atomicAdd(&hist[dig], __popc(mm));
            }
            __syncthreads();
            if (tid < 32) {
                // per-lane suffix sums over 8 bins, then warp scan
                int loc[8]; int ssum = 0;
                #pragma unroll
                for (int k = 7; k >= 0; k--) { ssum += hist[(lane << 3) + k]; loc[k] = ssum; }
                int incl = ssum;
                #pragma unroll
                for (int o = 1; o < 32; o <<= 1) {
                    int v = __shfl_up_sync(FULLM, incl, o);
                    if (lane >= o) incl += v;
                }
                int total = __shfl_sync(FULLM, incl, 31);
                int gt_lane = total - incl;
                #pragma unroll
                for (int k = 0; k < 8; k++) {
                    int bin = (lane << 3) + k;
                    int h = hist[bin];
                    int cgt = gt_lane + loc[k] - h;
                    if (h > 0 && above + cgt < DET && above + cgt + h >= DET) {
                        sel_bin = bin; sel_above = above + cgt; sel_cnt = h;
                    }
                }
            }
            __syncthreads();
            prefix |= ((unsigned)sel_bin) << shift;
            pmask |= 0xFFu << shift;
            above = sel_above;
            if (above + sel_cnt <= CANDCAP) break;
            __syncthreads();
        }
        thr = prefix;   // low unfixed bits are zero
    }

    // collect candidates >= thr (ballot-aggregated)
    if (tid == 0) ncand2 = 0;
    __syncthreads();
    #pragma unroll
    for (int i = 0; i < KMAX; i++) {
        bool c = hi[i] && (hi[i] >= thr);
        unsigned mb = __ballot_sync(FULLM, c);
        if (mb) {
            int ldr = __ffs(mb) - 1;
            int basep = 0;
            if (lane == ldr) basep = atomicAdd(&ncand2, __popc(mb));
            basep = __shfl_sync(FULLM, basep, ldr);
            if (c) {
                int pos = basep + __popc(mb & ((1u << lane) - 1u));
                if (pos < CANDCAP)
                    cand[pos] = ((unsigned long long)hi[i] << 32) | lo[i];
            }
        }
    }
    __syncthreads();
    int n2 = min(ncand2, CANDCAP);

    // rank-by-counting (all candidates distinct), scatter output rows
    // output layout (float32): bb [B,DET,4] | rr [B,DET,5] | sc [B,DET] | lab [B,DET]
    if (tid < n2) {
        unsigned long long mine = cand[tid];
        int r = 0;
        #pragma unroll 4
        for (int i = 0; i < n2; i++) r += (cand[i] > mine);
        if (r < DET) {
            unsigned khi = (unsigned)(mine >> 32);
            int fi = (int)(~(unsigned)mine);
            float val = __uint_as_float(khi ^ 0x80000000u);
            int cls = fi / P + 1;
            int gi = b * TOT + fi;
            int o = b * DET + r;
            float4 bx = g_bx4[gi];
            out[o * 4 + 0] = bx.x; out[o * 4 + 1] = bx.y;
            out[o * 4 + 2] = bx.z; out[o * 4 + 3] = bx.w;
            #pragma unroll
            for (int jj = 0; jj < 5; jj++)
                out[B * DET * 4 + o * 5 + jj] = g_pr_s[gi * 5 + jj];
            out[B * DET * 9 + o] = val;
            out[B * DET * 10 + o] = (float)cls;
        }
    }
    // zero-fill rows with no candidate
    if (tid >= n2 && tid < DET) {
        int o = b * DET + tid;
        #pragma unroll
        for (int jj = 0; jj < 4; jj++) out[o * 4 + jj] = 0.0f;
        #pragma unroll
        for (int jj = 0; jj < 5; jj++) out[B * DET * 4 + o * 5 + jj] = 0.0f;
        out[B * DET * 9 + o] = 0.0f;
        out[B * DET * 10 + o] = 0.0f;
    }

    __syncthreads();
    if (tid == 0) g_cnd_n[b] = 0;   // reset for next (deterministic) launch
}

// ---------------- launch ----------------
extern "C" void kernel_launch(void* const* d_in, const int* in_sizes, int n_in,
                              void* d_out, int out_size)
{
    const float* logits = (const float*)d_in[0];
    const float* regr   = (const float*)d_in[1];
    const float* rrects = (const float*)d_in[2];
    float* out = (float*)d_out;

    const int SMEM = P * (int)sizeof(float4)                 // sbb
                   + P * (int)sizeof(float)                  // cs
                   + P * (int)sizeof(int)                    // cidx
                   + 8 * P * (int)sizeof(float)              // ptsx+ptsy
                   + P * (int)sizeof(float)                  // areaS
                   + 16 * P * (int)sizeof(unsigned)          // sup
                   + SQ_CAP * (int)sizeof(int);              // squeue
    cudaFuncSetAttribute(k123_sortnms, cudaFuncAttributeMaxDynamicSharedMemorySize, SMEM);

    k123_sortnms<<<NGRP, P, SMEM>>>(logits, regr, rrects);
    k4_topk<<<B, 1024>>>(out);
}

// round 16
// speedup vs baseline: 1.1129x; 1.1129x over previous
#include <cuda_runtime.h>
#include <cuda_bf16.h>
#include <math.h>
#include <stdint.h>

#define B 2
#define P 512
#define C 21
#define REG 5
#define DET 100
#define NGRP (B*(C-1))          // 40
#define TOT ((C-1)*P)           // 10240 per image
#define SCORE_THRESH 0.05f
#define NMS_THR 0.5f
#define BBOX_CLIP 4.135166556742356f   // log(1000/16)
#define DEG2RAD 0.017453292519943295f
#define RAD2DEG 57.29577951308232f
#define IMW_M1 1023.0f
#define IMH_M1 799.0f
#define QCAP 131072
#define SQ_CAP 4096
#define FULLM 0xffffffffu
#define CCAP 512

// ---------------- device scratch ----------------
__device__ float  g_pr_s[NGRP * P * 5];          // rank-ordered proposals
__device__ float4 g_bx4[NGRP * P];               // rank-ordered clipped aabb
__device__ unsigned long long g_cand[B * TOT];   // kept candidates (key<<32 | ~fi)
__device__ int    g_cnd_n[B];                    // per-image candidate count (k4 resets)
__device__ int    g_queue[NGRP * QCAP];          // pair-queue overflow

// ---------------- exact quad-quad intersection area (matches reference) -----
__device__ float inter_area(const float* __restrict__ p1x, const float* __restrict__ p1y,
                            const float* __restrict__ p2x, const float* __restrict__ p2y)
{
    float px[8], py[8];
    #pragma unroll
    for (int i = 0; i < 4; i++) { px[i] = p1x[i]; py[i] = p1y[i]; }
    int n = 4;

    for (int k = 0; k < 4; k++) {
        float ax = p2x[k], ay = p2y[k];
        int k1 = (k + 1) & 3;
        float dx = p2x[k1] - ax, dy = p2y[k1] - ay;
        float qx[8], qy[8];
        int m = 0;
        for (int i = 0; i < n; i++) {
            float sx = px[i], sy = py[i];
            int ei = (i + 1 == n) ? 0 : (i + 1);
            float ex = px[ei], ey = py[ei];
            float cs = dx * (sy - ay) - dy * (sx - ax);
            float ce = dx * (ey - ay) - dy * (ex - ax);
            float denom = cs - ce;
            float t = cs / ((fabsf(denom) > 1e-12f) ? denom : 1e-12f);
            float ipx = sx + t * (ex - sx);
            float ipy = sy + t * (ey - sy);
            bool s_in = (cs >= 0.0f), e_in = (ce >= 0.0f);
            if (s_in != e_in) { int mm = m < 7 ? m : 7; qx[mm] = ipx; qy[mm] = ipy; m++; }
            if (e_in)         { int mm = m < 7 ? m : 7; qx[mm] = ex;  qy[mm] = ey;  m++; }
        }
        if (m > 8) m = 8;
        n = m;
        for (int i = 0; i < n; i++) { px[i] = qx[i]; py[i] = qy[i]; }
    }
    if (n < 3) return 0.0f;
    float acc = 0.0f;
    for (int i = 0; i < n; i++) {
        int k2 = (i + 1 == n) ? 0 : (i + 1);
        acc += px[i] * py[k2] - px[k2] * py[i];
    }
    return 0.5f * fabsf(acc);
}

// ---------------- kernel: decode + rank + rotated NMS per group -------------
__global__ __launch_bounds__(512)
void k123_sortnms(const float* __restrict__ logits,
                  const float* __restrict__ regr,
                  const float* __restrict__ rrects)
{
    int g = blockIdx.x;                 // 0..39
    int b = g / (C-1);
    int cls = g % (C-1) + 1;
    int tid = threadIdx.x;              // 0..511
    int lane = tid & 31;

    extern __shared__ float4 smf4[];
    float4* sbb  = smf4;                        // 512 float4 (mnx,mny,mxx,mxy)
    float*  cs   = (float*)(sbb + P);           // 512 compacted scores
    int*    cidx = (int*)(cs + P);              // 512 compacted orig idx
    float*  ptsx = (float*)(cidx + P);          // 512*4
    float*  ptsy = ptsx + 4 * P;                // 512*4
    float*  areaS= ptsy + 4 * P;                // 512
    unsigned* sup = (unsigned*)(areaS + P);     // 512*16
    int* squeue  = (int*)(sup + 16 * P);        // SQ_CAP
    __shared__ int vcnt, qcnt, Vsh;
    __shared__ unsigned dirty[16];
    __shared__ unsigned keepM[16];

    int row = b * P + tid;

    // ---- softmax score for (row, cls) ----
    const float* lg = &logits[row * C];
    float mx = lg[0];
    #pragma unroll
    for (int i = 1; i < C; i++) mx = fmaxf(mx, lg[i]);
    float ssum = 0.0f, ecls = 0.0f;
    #pragma unroll
    for (int i = 0; i < C; i++) {
        float e = expf(lg[i] - mx);
        ssum += e;
        if (i == cls) ecls = e;
    }
    float s = ecls / ssum;
    bool valid = s > SCORE_THRESH;

    // ---- decode own (row, cls) box into registers ----
    float pp[5];
    {
        float axc = rrects[row*5+0], ayc = rrects[row*5+1];
        float aw  = rrects[row*5+2], ah  = rrects[row*5+3];
        float aa  = rrects[row*5+4];
        const float* d = &regr[row * C * REG + cls * REG];
        float dx = d[0] / 10.0f;
        float dy = d[1] / 10.0f;
        float dw = fminf(d[2] / 5.0f, BBOX_CLIP);
        float dh = fminf(d[3] / 5.0f, BBOX_CLIP);
        float da = d[4] / 3.0f;
        pp[0] = dx * aw + axc;
        pp[1] = dy * ah + ayc;
        pp[2] = expf(dw) * aw;
        pp[3] = expf(dh) * ah;
        pp[4] = da * RAD2DEG + aa;
    }

    // ---- corners + aabb (registers) ----
    float th = pp[4] * DEG2RAD;
    float cth = cosf(th), sth = sinf(th);
    float hx = pp[2] * 0.5f, hy = pp[3] * 0.5f;
    float oxs[4] = {-hx, hx, hx, -hx};
    float oys[4] = {-hy, -hy, hy, hy};
    float cxx[4], cyy[4];
    float mnx = 1e30f, mny = 1e30f, mxx = -1e30f, mxy = -1e30f;
    #pragma unroll
    for (int i = 0; i < 4; i++) {
        float cx = pp[0] + cth * oxs[i] - sth * oys[i];
        float cy = pp[1] + sth * oxs[i] + cth * oys[i];
        cxx[i] = cx; cyy[i] = cy;
        mnx = fminf(mnx, cx); mxx = fmaxf(mxx, cx);
        mny = fminf(mny, cy); mxy = fmaxf(mxy, cy);
    }

    // ---- init shared ----
    if (tid == 0) { vcnt = 0; qcnt = 0; }
    if (tid < 16) dirty[tid] = 0u;
    #pragma unroll
    for (int k = 0; k < 16; k++) sup[k * P + tid] = 0u;
    __syncthreads();

    // ---- compact valid entries ----
    unsigned mbv = __ballot_sync(FULLM, valid);
    int wb = 0;
    if (lane == 0 && mbv) wb = atomicAdd(&vcnt, __popc(mbv));
    wb = __shfl_sync(FULLM, wb, 0);
    if (valid) {
        int p = wb + __popc(mbv & ((1u << lane) - 1u));
        cs[p] = s; cidx[p] = tid;
    }
    __syncthreads();
    int V = vcnt;
    if (tid == 0) Vsh = V;

    // ---- rank valid entries by (score desc, idx asc); scatter own data ----
    int rank = -1;
    if (valid) {
        int r = 0;
        #pragma unroll 4
        for (int i = 0; i < V; i++) {
            float o = cs[i];
            r += (o > s) || (o == s && cidx[i] < tid);
        }
        rank = r;
        #pragma unroll
        for (int i = 0; i < 4; i++) { ptsx[rank*4+i] = cxx[i]; ptsy[rank*4+i] = cyy[i]; }
        sbb[rank] = make_float4(mnx, mny, mxx, mxy);
        areaS[rank] = pp[2] * pp[3];
        #pragma unroll
        for (int k = 0; k < 5; k++) g_pr_s[(g * P + rank) * 5 + k] = pp[k];
        g_bx4[g * P + rank] = make_float4(
            fminf(fmaxf(mnx, 0.0f), IMW_M1),
            fminf(fmaxf(mny, 0.0f), IMH_M1),
            fminf(fmaxf(mxx, 0.0f), IMW_M1),
            fminf(fmaxf(mxy, 0.0f), IMH_M1));
    }
    __syncthreads();

    // ---- phase 1: AABB + IoU-upper-bound precheck -> pair queue ----
    long long M = (long long)V * (V - 1) / 2;
    if (M > 0) {
        int nIter = (int)((M + P - 1) / P);
        long long t = tid;
        int pi = 0, pj = 0;
        if (t < M) {
            pi = (int)((sqrtf(8.0f * (float)t + 1.0f) + 1.0f) * 0.5f);
            while ((long long)pi * (pi - 1) / 2 > t) pi--;
            while ((long long)(pi + 1) * pi / 2 <= t) pi++;
            pj = (int)(t - (long long)pi * (pi - 1) / 2);
        }
        for (int it = 0; it < nIter; it++) {
            bool push = false;
            if (t < M) {
                float4 bi = sbb[pi], bj = sbb[pj];
                float iw = fminf(bi.z, bj.z) - fmaxf(bi.x, bj.x);
                float ih = fminf(bi.w, bj.w) - fmaxf(bi.y, bj.y);
                if (iw > 0.0f && ih > 0.0f) {
                    float ai = areaS[pi], aj = areaS[pj];
                    float ub = fminf(iw * ih, fminf(ai, aj));
                    float bound = ub / (ai + aj - ub + 1e-8f);
                    push = bound > NMS_THR * 0.999f;   // conservative upper bound
                }
            }
            unsigned mb = __ballot_sync(FULLM, push);
            if (mb) {
                int ldr = __ffs(mb) - 1;
                int basep = 0;
                if (lane == ldr) basep = atomicAdd(&qcnt, __popc(mb));
                basep = __shfl_sync(FULLM, basep, ldr);
                if (push) {
                    int pos = basep + __popc(mb & ((1u << lane) - 1u));
                    int enc = (pi << 16) | pj;
                    if (pos < SQ_CAP) squeue[pos] = enc;
                    else g_queue[g * QCAP + (pos - SQ_CAP)] = enc;
                }
            }
            t += P;
            if (t < M) {
                pj += P;
                while (pj >= pi) { pj -= pi; pi++; }
            }
        }
    }
    __syncthreads();

    // ---- phase 2: exact IoU over surviving pairs ----
    int nq = qcnt;
    for (int q = tid; q < nq; q += blockDim.x) {
        int ij = (q < SQ_CAP) ? squeue[q] : g_queue[g * QCAP + (q - SQ_CAP)];
        int i = ij >> 16, j = ij & 0xffff;
        float inter = inter_area(&ptsx[i * 4], &ptsy[i * 4], &ptsx[j * 4], &ptsy[j * 4]);
        float iou = inter / (areaS[i] + areaS[j] - inter + 1e-8f);
        if (iou > NMS_THR) {
            atomicOr(&sup[i * 16 + (j >> 5)], 1u << (j & 31));
            atomicOr(&dirty[i >> 5], 1u << (i & 31));
        }
    }
    __syncthreads();

    // ---- phase 3: sparse greedy scan (warp 0, only dirty rows) ----
    if (tid < 32) {
        unsigned km = 0u;
        if (tid < 16) {
            int lo = tid * 32;
            int VV = Vsh;
            km = (VV >= lo + 32) ? 0xffffffffu : (VV > lo ? ((1u << (VV - lo)) - 1u) : 0u);
        }
        #pragma unroll
        for (int w = 0; w < 16; w++) {
            unsigned m = dirty[w];
            while (m) {
                int i = w * 32 + __ffs(m) - 1;
                m &= m - 1;
                unsigned srow = (tid < 16) ? sup[i * 16 + tid] : 0u;
                bool any = __any_sync(FULLM, (srow & km) != 0u);
                if (any && tid == (i >> 5)) km &= ~(1u << (i & 31));
            }
        }
        if (tid < 16) keepM[tid] = km;
    }
    __syncthreads();

    // ---- emit kept candidates to per-image list ----
    bool emit = valid && ((keepM[rank >> 5] >> (rank & 31)) & 1u);
    unsigned mb = __ballot_sync(FULLM, emit);
    if (mb) {
        int ldr = __ffs(mb) - 1;
        int basep = 0;
        if (lane == ldr) basep = atomicAdd(&g_cnd_n[b], __popc(mb));
        basep = __shfl_sync(FULLM, basep, ldr);
        if (emit) {
            int pos = basep + __popc(mb & ((1u << lane) - 1u));
            int fi = (cls - 1) * P + rank;
            unsigned kk = __float_as_uint(s) ^ 0x80000000u;   // s > 0 monotone key
            g_cand[b * TOT + pos] =
                ((unsigned long long)kk << 32) | (unsigned)(~fi);
        }
    }
}

// ---------------- kernel 4: histogram top-100 select + output ----------------
__global__ __launch_bounds__(1024)
void k4_topk(float* __restrict__ out)
{
    int b = blockIdx.x;
    int tid = threadIdx.x;
    int lane = tid & 31;
    int wid = tid >> 5;

    __shared__ int hist[4096];
    __shared__ int warpsum[32];
    __shared__ int nc_sh;
    __shared__ int selB, selAbove, selCnt, selFound;
    __shared__ int ncand2;
    __shared__ unsigned long long cand[CCAP];

    if (tid == 0) { nc_sh = g_cnd_n[b]; ncand2 = 0; }
    #pragma unroll
    for (int k = 0; k < 4; k++) hist[tid + (k << 10)] = 0;
    __syncthreads();
    int nc = nc_sh;

    unsigned prefix = 0u, pmask = 0u;
    unsigned thr = 0u;
    int above = 0;

    // level 0: digit = bits [20:32) (includes sign/MSB). level 1: bits [8:20).
    for (int level = 0; level < 2; level++) {
        int shift = level ? 8 : 20;
        if (level) {
            #pragma unroll
            for (int k = 0; k < 4; k++) hist[tid + (k << 10)] = 0;
            if (tid == 0) selFound = 0;
            __syncthreads();
            for (int pos = tid; pos < nc; pos += 1024) {
                unsigned hi = (unsigned)(g_cand[b * TOT + pos] >> 32);
                if ((hi & pmask) == prefix) atomicAdd(&hist[(hi >> 8) & 0xFFF], 1);
            }
            __syncthreads();
        } else {
            if (tid == 0) selFound = 0;
            __syncthreads();
            for (int pos = tid; pos < nc; pos += 1024) {
                unsigned hi = (unsigned)(g_cand[b * TOT + pos] >> 32);
                atomicAdd(&hist[hi >> 20], 1);
            }
            __syncthreads();
        }

        // block suffix-count: each thread owns bins [4t, 4t+3]
        int base = tid << 2;
        int h0 = hist[base], h1 = hist[base + 1], h2 = hist[base + 2], h3 = hist[base + 3];
        int st = h0 + h1 + h2 + h3;
        int incl = st;
        #pragma unroll
        for (int o = 1; o < 32; o <<= 1) {
            int v = __shfl_up_sync(FULLM, incl, o);
            if (lane >= o) incl += v;
        }
        if (lane == 31) warpsum[wid] = incl;
        __syncthreads();
        if (tid < 32) {
            int wi = warpsum[lane];
            #pragma unroll
            for (int o = 1; o < 32; o <<= 1) {
                int u = __shfl_up_sync(FULLM, wi, o);
                if (lane >= o) wi += u;
            }
            warpsum[lane] = wi;   // inclusive warp prefix
        }
        __syncthreads();
        int offs = (wid > 0) ? warpsum[wid - 1] : 0;
        int inclusive = incl + offs;
        int total = warpsum[31];
        int S = total - inclusive;        // count in bins owned by higher threads
        int cgt3 = S;
        int cgt2 = cgt3 + h3;
        int cgt1 = cgt2 + h2;
        int cgt0 = cgt1 + h1;
        int hh[4] = {h0, h1, h2, h3};
        int cg[4] = {cgt0, cgt1, cgt2, cgt3};
        #pragma unroll
        for (int k = 0; k < 4; k++) {
            if (hh[k] > 0 && above + cg[k] < DET && above + cg[k] + hh[k] >= DET) {
                selB = base + k; selAbove = above + cg[k]; selCnt = hh[k]; selFound = 1;
            }
        }
        __syncthreads();

        if (!selFound) { thr = 0u; break; }        // total kept < DET: take all
        prefix |= ((unsigned)selB) << shift;
        pmask |= 0xFFFu << shift;
        above = selAbove;
        if (selAbove + selCnt <= CCAP || level == 1) { thr = prefix; break; }
        __syncthreads();
    }

    // collect candidates with key >= thr (ballot-aggregated; uniform loop)
    for (int pos0 = 0; pos0 < nc; pos0 += 1024) {
        int pos = pos0 + tid;
        bool c = false;
        unsigned long long u = 0ull;
        if (pos < nc) {
            u = g_cand[b * TOT + pos];
            c = ((unsigned)(u >> 32)) >= thr;
        }
        unsigned mb = __ballot_sync(FULLM, c);
        if (mb) {
            int ldr = __ffs(mb) - 1;
            int basep = 0;
            if (lane == ldr) basep = atomicAdd(&ncand2, __popc(mb));
            basep = __shfl_sync(FULLM, basep, ldr);
            if (c) {
                int p = basep + __popc(mb & ((1u << lane) - 1u));
                if (p < CCAP) cand[p] = u;
            }
        }
    }
    __syncthreads();
    int n2 = min(ncand2, CCAP);

    // rank-by-counting (u64 keys distinct), scatter output rows
    // output layout (float32): bb [B,DET,4] | rr [B,DET,5] | sc [B,DET] | lab [B,DET]
    if (tid < n2) {
        unsigned long long mine = cand[tid];
        int r = 0;
        #pragma unroll 4
        for (int i = 0; i < n2; i++) r += (cand[i] > mine);
        if (r < DET) {
            unsigned khi = (unsigned)(mine >> 32);
            int fi = (int)(~(unsigned)mine);
            float val = __uint_as_float(khi ^ 0x80000000u);
            int cls = fi / P + 1;
            int gi = b * TOT + fi;
            int o = b * DET + r;
            float4 bx = g_bx4[gi];
            out[o * 4 + 0] = bx.x; out[o * 4 + 1] = bx.y;
            out[o * 4 + 2] = bx.z; out[o * 4 + 3] = bx.w;
            #pragma unroll
            for (int jj = 0; jj < 5; jj++)
                out[B * DET * 4 + o * 5 + jj] = g_pr_s[gi * 5 + jj];
            out[B * DET * 9 + o] = val;
            out[B * DET * 10 + o] = (float)cls;
        }
    }
    // zero-fill rows with no candidate
    if (tid >= n2 && tid < DET) {
        int o = b * DET + tid;
        #pragma unroll
        for (int jj = 0; jj < 4; jj++) out[o * 4 + jj] = 0.0f;
        #pragma unroll
        for (int jj = 0; jj < 5; jj++) out[B * DET * 4 + o * 5 + jj] = 0.0f;
        out[B * DET * 9 + o] = 0.0f;
        out[B * DET * 10 + o] = 0.0f;
    }

    __syncthreads();
    if (tid == 0) g_cnd_n[b] = 0;   // reset for deterministic replay
}

// ---------------- launch ----------------
extern "C" void kernel_launch(void* const* d_in, const int* in_sizes, int n_in,
                              void* d_out, int out_size)
{
    const float* logits = (const float*)d_in[0];
    const float* regr   = (const float*)d_in[1];
    const float* rrects = (const float*)d_in[2];
    float* out = (float*)d_out;

    const int SMEM = P * (int)sizeof(float4)                 // sbb
                   + P * (int)sizeof(float)                  // cs
                   + P * (int)sizeof(int)                    // cidx
                   + 8 * P * (int)sizeof(float)              // ptsx+ptsy
                   + P * (int)sizeof(float)                  // areaS
                   + 16 * P * (int)sizeof(unsigned)          // sup
                   + SQ_CAP * (int)sizeof(int);              // squeue
    cudaFuncSetAttribute(k123_sortnms, cudaFuncAttributeMaxDynamicSharedMemorySize, SMEM);

    k123_sortnms<<<NGRP, P, SMEM>>>(logits, regr, rrects);
    k4_topk<<<B, 1024>>>(out);
}